// round 3
// baseline (speedup 1.0000x reference)
#include <cuda_runtime.h>
#include <cuda_bf16.h>
#include <cstdint>

// Problem constants (match reference)
#define LVL   32
#define PINS  131072
#define NNETS 1000000
#define TPER  10.0f

#define NBLK  128
#define NTHR  1024   // NBLK*NTHR == PINS exactly: one thread per pin per level

// ---- software grid barrier state (zero-init; restored to 0 at kernel end) ----
__device__ unsigned g_count = 0;
__device__ volatile unsigned g_release = 0;

static __device__ __forceinline__ void grid_bar(unsigned target) {
    __syncthreads();
    if (threadIdx.x == 0) {
        // release: gpu-scope fence (emits CCTL.IVALL on sm_103a -> also
        // invalidates this SM's L1D). Cumulative over the block via bar.sync.
        __threadfence();
        unsigned a = atomicAdd(&g_count, 1u);
        if (a == NBLK - 1) {
            g_count = 0;          // all arrived; safe to reset for next barrier
            __threadfence();
            g_release = target;   // release the grid
        } else {
            while (g_release < target) { }
            __threadfence();      // acquire + L1D invalidate before data reads
        }
    }
    __syncthreads();
}

static __device__ __forceinline__ void atomicMinFloat(float* addr, float val) {
    // Signed/unsigned trick; initial value (TPER) positive -> invariant holds.
    if (val >= 0.0f) {
        atomicMin((int*)addr, __float_as_int(val));
    } else {
        atomicMax((unsigned int*)addr, __float_as_uint(val));
    }
}

__global__ void __launch_bounds__(NTHR, 1)
sta_persistent_kernel(const float* __restrict__ delays,
                      const int2*  __restrict__ src,
                      const int2*  __restrict__ net,
                      const unsigned int* __restrict__ mask,  // 4-byte bool words
                      float* __restrict__ out,
                      long long out_size) {
    const int tid = blockIdx.x * NTHR + threadIdx.x;   // == pin index, 0..PINS-1
    const long long LP = (long long)LVL * PINS;

    float* arr = out;        // [0, LP)
    float* req = out + LP;   // [LP, 2LP)

    // ---- init: arrival level 0 = delays, required = TPER everywhere ----
    arr[tid] = delays[tid];
    #pragma unroll
    for (int l = 0; l < LVL; ++l)
        req[(long long)l * PINS + tid] = TPER;
    grid_bar(1);

    // ---- forward arrival propagation ----
    for (int l = 1; l < LVL; ++l) {
        float d = delays[l * PINS + tid];
        int2  s = src[(l - 1) * PINS + tid];
        int2  n = net[(l - 1) * PINS + tid];
        const float* ap = arr + (l - 1) * PINS;

        float m = d;
        if (mask[n.x] == 0u) m = fmaxf(m, ap[s.x] + d);
        if (mask[n.y] == 0u) m = fmaxf(m, ap[s.y] + d);
        arr[l * PINS + tid] = m;

        grid_bar(1 + l);   // targets 2..32
    }

    // ---- backward required propagation (scatter-min) ----
    for (int l = LVL - 2; l >= 0; --l) {
        // req[l+1] final at this point; read L2-coherent (atomics updated L2)
        float c = __ldcg(&req[(l + 1) * PINS + tid]) - delays[(l + 1) * PINS + tid];
        int2  s = src[l * PINS + tid];
        int2  n = net[l * PINS + tid];
        float* rl = req + (long long)l * PINS;

        if (mask[n.x] == 0u) atomicMinFloat(rl + s.x, c);
        if (mask[n.y] == 0u) atomicMinFloat(rl + s.y, c);

        grid_bar(32 + (LVL - 1 - l));   // targets 33..63
    }

    // ---- final: slacks + mask re-emit ----
    #pragma unroll
    for (int l = 0; l < LVL; ++l) {
        long long i = (long long)l * PINS + tid;
        long long o = 2 * LP + i;
        if (o < out_size) out[o] = __ldcg(&req[i]) - arr[i];
    }
    for (int i = tid; i < NNETS; i += PINS) {
        long long o = 3 * LP + i;
        if (o < out_size) out[o] = mask[i] ? 1.0f : 0.0f;
    }

    // ---- cleanup: arrive-only barrier; last arriver resets state ----
    __syncthreads();
    if (threadIdx.x == 0) {
        unsigned a = atomicAdd(&g_count, 1u);
        if (a == NBLK - 1) {
            g_count = 0;
            __threadfence();
            g_release = 0;
        }
    }
}

extern "C" void kernel_launch(void* const* d_in, const int* in_sizes, int n_in,
                              void* d_out, int out_size) {
    const float*        delays = (const float*)d_in[0];
    const int2*         src    = (const int2*)d_in[1];
    const int2*         net    = (const int2*)d_in[2];
    const unsigned int* mask   = (const unsigned int*)d_in[3];

    sta_persistent_kernel<<<NBLK, NTHR>>>(delays, src, net, mask,
                                          (float*)d_out, (long long)out_size);
}

// round 4
// speedup vs baseline: 1.4259x; 1.4259x over previous
#include <cuda_runtime.h>
#include <cuda_bf16.h>
#include <cstdint>

// Problem constants (match reference)
#define LVL   32
#define PINS  131072
#define NNETS 1000000
#define TPER  10.0f

// Per-arc validity computed in the forward pass, reused by backward.
// bit0 = arc 0 valid, bit1 = arc 1 valid.  (L-1)*P bytes = ~4MB.
__device__ unsigned char g_valid[(LVL - 1) * PINS];

static __device__ __forceinline__ void atomicMinFloat(float* addr, float val) {
    // Signed/unsigned trick. Initial value (TPER=10.0) is positive; handles
    // mixed signs correctly: signed-int min orders negatives below positives,
    // unsigned max orders negatives reversed among themselves.
    if (val >= 0.0f) {
        atomicMin((int*)addr, __float_as_int(val));
    } else {
        atomicMax((unsigned int*)addr, __float_as_uint(val));
    }
}

// init: arrival[0] = delays[0:P], required[0] = TPER (levels 1..L-1 req
// are initialized by their fwd kernels).
__global__ void sta_init_kernel(const float* __restrict__ delays,
                                float* __restrict__ arr,
                                float* __restrict__ req) {
    int p = blockIdx.x * blockDim.x + threadIdx.x;
    if (p < PINS) {
        arr[p] = delays[p];
        req[p] = TPER;
    }
}

// Forward level l (1..L-1): compute arrival, init req[l]=TPER, record validity.
__global__ void sta_fwd_kernel(const float* __restrict__ delays,
                               const int2*  __restrict__ src,
                               const int2*  __restrict__ net,
                               const unsigned int* __restrict__ mask, // 4B bool words
                               float* __restrict__ arr,
                               float* __restrict__ req,
                               int l) {
    int p = blockIdx.x * blockDim.x + threadIdx.x;
    if (p >= PINS) return;

    const int a = (l - 1) * PINS + p;
    float d = __ldg(&delays[l * PINS + p]);
    int2  s = __ldg(&src[a]);
    int2  n = __ldg(&net[a]);

    unsigned v0 = (mask[n.x] == 0u) ? 1u : 0u;
    unsigned v1 = (mask[n.y] == 0u) ? 1u : 0u;

    const float* ap = arr + (l - 1) * PINS;
    float m = d;
    if (v0) m = fmaxf(m, __ldg(&ap[s.x]) + d);
    if (v1) m = fmaxf(m, __ldg(&ap[s.y]) + d);

    arr[l * PINS + p] = m;
    req[l * PINS + p] = TPER;
    g_valid[a] = (unsigned char)(v0 | (v1 << 1));
}

// Backward level l (L-2..0): slack[l+1] = req[l+1]-arr[l+1] (req[l+1] is
// final here), then scatter-min (req[l+1]-delays[l+1]) into req[l] via the
// recorded valid bits. No net/mask access at all.
__global__ void sta_bwd_kernel(const float* __restrict__ delays,
                               const int2*  __restrict__ src,
                               const float* __restrict__ arr,
                               float* __restrict__ req,
                               float* __restrict__ slack,
                               int l) {
    int p = blockIdx.x * blockDim.x + threadIdx.x;
    if (p >= PINS) return;

    const int up = (l + 1) * PINS + p;
    float r1 = __ldcg(&req[up]);             // L2-coherent (atomics live in L2)
    float d1 = __ldg(&delays[up]);
    slack[up] = r1 - __ldg(&arr[up]);

    float c = r1 - d1;
    const int a = l * PINS + p;
    unsigned char v = g_valid[a];
    int2 s = __ldg(&src[a]);

    float* rl = req + l * PINS;
    if (v & 1u) atomicMinFloat(rl + s.x, c);
    if (v & 2u) atomicMinFloat(rl + s.y, c);
}

// Epilogue: slack[0] (req[0] final after bwd l=0) + mask re-emit as 0/1 float.
__global__ void sta_epilogue_kernel(const float* __restrict__ arr,
                                    const float* __restrict__ req,
                                    const unsigned int* __restrict__ mask,
                                    float* __restrict__ slack,
                                    float* __restrict__ mask_out,
                                    long long mask_out_room) {
    int i = blockIdx.x * blockDim.x + threadIdx.x;
    if (i < PINS) {
        slack[i] = __ldcg(&req[i]) - arr[i];
    }
    if (i < NNETS && i < mask_out_room) {
        mask_out[i] = mask[i] ? 1.0f : 0.0f;
    }
}

extern "C" void kernel_launch(void* const* d_in, const int* in_sizes, int n_in,
                              void* d_out, int out_size) {
    const float*        delays = (const float*)d_in[0];
    const int2*         src    = (const int2*)d_in[1];   // K=2 packed pairs
    const int2*         net    = (const int2*)d_in[2];
    const unsigned int* mask   = (const unsigned int*)d_in[3];

    float* out = (float*)d_out;
    const long long LP = (long long)LVL * PINS;

    float* arr      = out;           // [0,   LP)
    float* req      = out + LP;      // [LP,  2LP)
    float* slack    = out + 2 * LP;  // [2LP, 3LP)
    float* mask_out = out + 3 * LP;  // [3LP, 3LP+NNETS)
    long long mask_room = (long long)out_size - 3 * LP;

    const int T = 256;
    const int blocksP = (PINS + T - 1) / T;   // 512

    sta_init_kernel<<<blocksP, T>>>(delays, arr, req);

    for (int l = 1; l < LVL; ++l)
        sta_fwd_kernel<<<blocksP, T>>>(delays, src, net, mask, arr, req, l);

    for (int l = LVL - 2; l >= 0; --l)
        sta_bwd_kernel<<<blocksP, T>>>(delays, src, arr, req, slack, l);

    int blocksE = (NNETS + T - 1) / T;        // covers both PINS and NNETS
    sta_epilogue_kernel<<<blocksE, T>>>(arr, req, mask, slack, mask_out, mask_room);
}

// round 5
// speedup vs baseline: 1.4482x; 1.0156x over previous
#include <cuda_runtime.h>
#include <cuda_bf16.h>
#include <cstdint>

// Problem constants (match reference)
#define LVL   32
#define PINS  131072
#define NNETS 1000000
#define TPER  10.0f

// Per-arc validity, computed once upfront: bit0 = arc0 valid, bit1 = arc1 valid.
__device__ unsigned char g_valid[(LVL - 1) * PINS];

static __device__ __forceinline__ void atomicMinFloat(float* addr, float val) {
    // Signed/unsigned trick; initial value (TPER=10.0) positive.
    if (val >= 0.0f) {
        atomicMin((int*)addr, __float_as_int(val));
    } else {
        atomicMax((unsigned int*)addr, __float_as_uint(val));
    }
}

// ---------------------------------------------------------------------------
// Precompute (one big launch, bandwidth-bound, off the sequential path):
//   - valid bits for all (L-1)*P arc pairs (net load + mask gather)
//   - req[*] = TPER for all levels
//   - arr[0] = delays[0]
//   - mask re-emitted as 0/1 float
// ---------------------------------------------------------------------------
__global__ void sta_pre_kernel(const float* __restrict__ delays,
                               const int2*  __restrict__ net,
                               const unsigned int* __restrict__ mask,
                               float* __restrict__ arr,
                               float* __restrict__ req,
                               float* __restrict__ mask_out,
                               long long mask_out_room) {
    int i = blockIdx.x * blockDim.x + threadIdx.x;   // 0 .. L*P-1

    if (i < LVL * PINS) {
        req[i] = TPER;
        if (i < PINS) arr[i] = delays[i];
    }
    if (i < (LVL - 1) * PINS) {
        int2 n = __ldg(&net[i]);
        unsigned v0 = (mask[n.x] == 0u) ? 1u : 0u;
        unsigned v1 = (mask[n.y] == 0u) ? 2u : 0u;
        g_valid[i] = (unsigned char)(v0 | v1);
    }
    if (i < NNETS && i < mask_out_room) {
        mask_out[i] = mask[i] ? 1.0f : 0.0f;
    }
}

// ---------------------------------------------------------------------------
// Forward level l (1..L-1): 2 pins per thread, vector loads.
// arr[l][p] = max(d, valid ? arr[l-1][src]+d)
// ---------------------------------------------------------------------------
__global__ void sta_fwd_kernel(const float* __restrict__ delays,
                               const int2*  __restrict__ src,
                               float* __restrict__ arr,
                               int l) {
    int t = blockIdx.x * blockDim.x + threadIdx.x;   // 0 .. PINS/2-1
    if (t >= PINS / 2) return;

    const float* ap = arr + (l - 1) * PINS;

    float2 d  = ((const float2*)(delays + l * PINS))[t];
    int4   s  = ((const int4*)(src + (l - 1) * PINS))[t];      // two int2 pairs
    uchar2 vv = ((const uchar2*)(g_valid + (l - 1) * PINS))[t];

    // issue all four gathers before consuming (maximize MLP)
    float a0 = (vv.x & 1u) ? __ldg(&ap[s.x]) : 0.0f;
    float a1 = (vv.x & 2u) ? __ldg(&ap[s.y]) : 0.0f;
    float b0 = (vv.y & 1u) ? __ldg(&ap[s.z]) : 0.0f;
    float b1 = (vv.y & 2u) ? __ldg(&ap[s.w]) : 0.0f;

    float m0 = d.x;
    if (vv.x & 1u) m0 = fmaxf(m0, a0 + d.x);
    if (vv.x & 2u) m0 = fmaxf(m0, a1 + d.x);
    float m1 = d.y;
    if (vv.y & 1u) m1 = fmaxf(m1, b0 + d.y);
    if (vv.y & 2u) m1 = fmaxf(m1, b1 + d.y);

    ((float2*)(arr + l * PINS))[t] = make_float2(m0, m1);
}

// ---------------------------------------------------------------------------
// Backward level l (L-2..0): 2 pins per thread.
// slack[l+1] = req[l+1]-arr[l+1]; scatter-min (req[l+1]-delays[l+1]) into req[l].
// ---------------------------------------------------------------------------
__global__ void sta_bwd_kernel(const float* __restrict__ delays,
                               const int2*  __restrict__ src,
                               const float* __restrict__ arr,
                               float* __restrict__ req,
                               float* __restrict__ slack,
                               int l) {
    int t = blockIdx.x * blockDim.x + threadIdx.x;
    if (t >= PINS / 2) return;

    const int up = (l + 1) * PINS;
    float2 r1 = make_float2(__ldcg(&req[up + 2 * t]), __ldcg(&req[up + 2 * t + 1]));
    float2 d1 = ((const float2*)(delays + up))[t];
    float2 a1 = ((const float2*)(arr + up))[t];
    ((float2*)(slack + up))[t] = make_float2(r1.x - a1.x, r1.y - a1.y);

    float c0 = r1.x - d1.x;
    float c1 = r1.y - d1.y;

    int4   s  = ((const int4*)(src + l * PINS))[t];
    uchar2 vv = ((const uchar2*)(g_valid + l * PINS))[t];

    float* rl = req + (long long)l * PINS;
    if (vv.x & 1u) atomicMinFloat(rl + s.x, c0);
    if (vv.x & 2u) atomicMinFloat(rl + s.y, c0);
    if (vv.y & 1u) atomicMinFloat(rl + s.z, c1);
    if (vv.y & 2u) atomicMinFloat(rl + s.w, c1);
}

// Epilogue: slack[0] (req[0] final after bwd l=0).
__global__ void sta_epilogue_kernel(const float* __restrict__ arr,
                                    const float* __restrict__ req,
                                    float* __restrict__ slack) {
    int t = blockIdx.x * blockDim.x + threadIdx.x;
    if (t >= PINS / 2) return;
    float r0 = __ldcg(&req[2 * t]);
    float r1 = __ldcg(&req[2 * t + 1]);
    float2 a = ((const float2*)arr)[t];
    ((float2*)slack)[t] = make_float2(r0 - a.x, r1 - a.y);
}

extern "C" void kernel_launch(void* const* d_in, const int* in_sizes, int n_in,
                              void* d_out, int out_size) {
    const float*        delays = (const float*)d_in[0];
    const int2*         src    = (const int2*)d_in[1];
    const int2*         net    = (const int2*)d_in[2];
    const unsigned int* mask   = (const unsigned int*)d_in[3];

    float* out = (float*)d_out;
    const long long LP = (long long)LVL * PINS;

    float* arr      = out;           // [0,   LP)
    float* req      = out + LP;      // [LP,  2LP)
    float* slack    = out + 2 * LP;  // [2LP, 3LP)
    float* mask_out = out + 3 * LP;  // [3LP, 3LP+NNETS)
    long long mask_room = (long long)out_size - 3 * LP;

    const int T = 256;

    // precompute: covers max(L*P, NNETS) indices
    int blocksPre = (int)((LP + T - 1) / T);      // 16384 (L*P > NNETS)
    sta_pre_kernel<<<blocksPre, T>>>(delays, net, mask, arr, req, mask_out, mask_room);

    const int blocksH = (PINS / 2 + T - 1) / T;   // 256

    for (int l = 1; l < LVL; ++l)
        sta_fwd_kernel<<<blocksH, T>>>(delays, src, arr, l);

    for (int l = LVL - 2; l >= 0; --l)
        sta_bwd_kernel<<<blocksH, T>>>(delays, src, arr, req, slack, l);

    sta_epilogue_kernel<<<blocksH, T>>>(arr, req, slack);
}

// round 6
// speedup vs baseline: 2.1487x; 1.4837x over previous
#include <cuda_runtime.h>
#include <cuda_bf16.h>
#include <cstdint>

// Problem constants (match reference)
#define LVL   32
#define PINS  131072
#define NNETS 1000000
#define TPER  10.0f

// Per-arc validity, computed once upfront: bit0 = arc0 valid, bit1 = arc1 valid.
__device__ unsigned char g_valid[(LVL - 1) * PINS];

static __device__ __forceinline__ void atomicMinFloat(float* addr, float val) {
    // Signed/unsigned trick; initial value (TPER=10.0) positive.
    if (val >= 0.0f) {
        atomicMin((int*)addr, __float_as_int(val));
    } else {
        atomicMax((unsigned int*)addr, __float_as_uint(val));
    }
}

// ---------------------------------------------------------------------------
// Precompute: valid bits for all arcs, req[*]=TPER, arr[0]=delays[0], mask out.
// ---------------------------------------------------------------------------
__global__ void sta_pre_kernel(const float* __restrict__ delays,
                               const int2*  __restrict__ net,
                               const unsigned int* __restrict__ mask,
                               float* __restrict__ arr,
                               float* __restrict__ req,
                               float* __restrict__ mask_out,
                               long long mask_out_room) {
    int i = blockIdx.x * blockDim.x + threadIdx.x;   // 0 .. L*P-1
    if (i < LVL * PINS) {
        req[i] = TPER;
        if (i < PINS) arr[i] = delays[i];
    }
    if (i < (LVL - 1) * PINS) {
        int2 n = __ldg(&net[i]);
        unsigned v0 = (mask[n.x] == 0u) ? 1u : 0u;
        unsigned v1 = (mask[n.y] == 0u) ? 2u : 0u;
        g_valid[i] = (unsigned char)(v0 | v1);
    }
    if (i < NNETS && i < mask_out_room) {
        mask_out[i] = mask[i] ? 1.0f : 0.0f;
    }
}

// ---------------------------------------------------------------------------
// Forward level l: front-load independent streams, PDL-sync, gather, store.
// ---------------------------------------------------------------------------
__global__ void sta_fwd_kernel(const float* __restrict__ delays,
                               const int2*  __restrict__ src,
                               float* __restrict__ arr,
                               int l) {
    int t = blockIdx.x * blockDim.x + threadIdx.x;   // 0 .. PINS/2-1
    if (t >= PINS / 2) return;

    // independent of predecessor kernel:
    float2 d  = ((const float2*)(delays + l * PINS))[t];
    int4   s  = ((const int4*)(src + (l - 1) * PINS))[t];
    uchar2 vv = ((const uchar2*)(g_valid + (l - 1) * PINS))[t];

#if __CUDA_ARCH__ >= 900
    cudaGridDependencySynchronize();
    cudaTriggerProgrammaticLaunchCompletion();   // let next level ramp now
#endif

    const float* ap = arr + (l - 1) * PINS;
    float a0 = (vv.x & 1u) ? __ldg(&ap[s.x]) : 0.0f;
    float a1 = (vv.x & 2u) ? __ldg(&ap[s.y]) : 0.0f;
    float b0 = (vv.y & 1u) ? __ldg(&ap[s.z]) : 0.0f;
    float b1 = (vv.y & 2u) ? __ldg(&ap[s.w]) : 0.0f;

    float m0 = d.x;
    if (vv.x & 1u) m0 = fmaxf(m0, a0 + d.x);
    if (vv.x & 2u) m0 = fmaxf(m0, a1 + d.x);
    float m1 = d.y;
    if (vv.y & 1u) m1 = fmaxf(m1, b0 + d.y);
    if (vv.y & 2u) m1 = fmaxf(m1, b1 + d.y);

    ((float2*)(arr + l * PINS))[t] = make_float2(m0, m1);
}

// ---------------------------------------------------------------------------
// Backward level l: req only (no slack here -> independent of fwd chain).
// ---------------------------------------------------------------------------
__global__ void sta_bwd_kernel(const float* __restrict__ delays,
                               const int2*  __restrict__ src,
                               float* __restrict__ req,
                               int l) {
    int t = blockIdx.x * blockDim.x + threadIdx.x;
    if (t >= PINS / 2) return;

    const int up = (l + 1) * PINS;
    float2 d1 = ((const float2*)(delays + up))[t];
    int4   s  = ((const int4*)(src + l * PINS))[t];
    uchar2 vv = ((const uchar2*)(g_valid + l * PINS))[t];

#if __CUDA_ARCH__ >= 900
    cudaGridDependencySynchronize();
    cudaTriggerProgrammaticLaunchCompletion();
#endif

    float2 r1 = __ldcg((const float2*)(req + up) + t);
    float c0 = r1.x - d1.x;
    float c1 = r1.y - d1.y;

    float* rl = req + (long long)l * PINS;
    if (vv.x & 1u) atomicMinFloat(rl + s.x, c0);
    if (vv.x & 2u) atomicMinFloat(rl + s.y, c0);
    if (vv.y & 1u) atomicMinFloat(rl + s.z, c1);
    if (vv.y & 2u) atomicMinFloat(rl + s.w, c1);
}

// Epilogue: slack for ALL levels (both chains complete here).
__global__ void sta_epilogue_kernel(const float* __restrict__ arr,
                                    const float* __restrict__ req,
                                    float* __restrict__ slack) {
    int t = blockIdx.x * blockDim.x + threadIdx.x;
    if (t >= LVL * PINS / 2) return;
    float2 r = ((const float2*)req)[t];
    float2 a = ((const float2*)arr)[t];
    ((float2*)slack)[t] = make_float2(r.x - a.x, r.y - a.y);
}

// ---------------------------------------------------------------------------
template <typename... Args>
static void launch_pdl(cudaStream_t st, dim3 grid, dim3 block, bool pdl,
                       void (*kern)(Args...), Args... args) {
    cudaLaunchConfig_t cfg = {};
    cfg.gridDim = grid;
    cfg.blockDim = block;
    cfg.stream = st;
    cudaLaunchAttribute at[1];
    if (pdl) {
        at[0].id = cudaLaunchAttributeProgrammaticStreamSerialization;
        at[0].val.programmaticStreamSerializationAllowed = 1;
        cfg.attrs = at;
        cfg.numAttrs = 1;
    }
    cudaLaunchKernelEx(&cfg, kern, args...);
}

extern "C" void kernel_launch(void* const* d_in, const int* in_sizes, int n_in,
                              void* d_out, int out_size) {
    const float*        delays = (const float*)d_in[0];
    const int2*         src    = (const int2*)d_in[1];
    const int2*         net    = (const int2*)d_in[2];
    const unsigned int* mask   = (const unsigned int*)d_in[3];

    float* out = (float*)d_out;
    const long long LP = (long long)LVL * PINS;

    float* arr      = out;           // [0,   LP)
    float* req      = out + LP;      // [LP,  2LP)
    float* slack    = out + 2 * LP;  // [2LP, 3LP)
    float* mask_out = out + 3 * LP;  // [3LP, 3LP+NNETS)
    long long mask_room = (long long)out_size - 3 * LP;

    cudaStream_t s0 = (cudaStream_t)0;   // harness/capture stream

    // second stream + fork/join events (host-side resources only; kernel_launch
    // is invoked a bounded number of times, not per graph replay)
    cudaStream_t s2;
    cudaStreamCreateWithFlags(&s2, cudaStreamNonBlocking);
    cudaEvent_t evFork, evJoin;
    cudaEventCreateWithFlags(&evFork, cudaEventDisableTiming);
    cudaEventCreateWithFlags(&evJoin, cudaEventDisableTiming);

    const int T = 128;
    const int blocksH = (PINS / 2 + T - 1) / T;          // 512

    // precompute
    {
        int blocksPre = (int)((LP + 255) / 256);
        sta_pre_kernel<<<blocksPre, 256, 0, s0>>>(delays, net, mask, arr, req,
                                                  mask_out, mask_room);
    }

    // fork bwd chain onto s2
    cudaEventRecord(evFork, s0);
    cudaStreamWaitEvent(s2, evFork, 0);

    // forward chain (s0), PDL-overlapped
    for (int l = 1; l < LVL; ++l)
        launch_pdl(s0, dim3(blocksH), dim3(T), true,
                   sta_fwd_kernel, delays, src, arr, l);

    // backward chain (s2), PDL-overlapped
    for (int l = LVL - 2; l >= 0; --l)
        launch_pdl(s2, dim3(blocksH), dim3(T), l != LVL - 2,
                   sta_bwd_kernel, delays, src, req, l);

    // join
    cudaEventRecord(evJoin, s2);
    cudaStreamWaitEvent(s0, evJoin, 0);

    // slack for all levels
    {
        int blocksE = (int)((LP / 2 + 255) / 256);
        sta_epilogue_kernel<<<blocksE, 256, 0, s0>>>(arr, req, slack);
    }
}